// round 7
// baseline (speedup 1.0000x reference)
#include <cuda_runtime.h>

// TransOp_expm: out[b,s] = expm(sum_m c[b,m]*psi[m,s]) @ x[b,s]
// B=8192, DICT=64, N=8, M=16. Pure fp32, packed f32x2 (two b's per thread).
// One vector-level scaling step: expm(A)x = expm(A/2)(expm(A/2)x),
// each half-pass via Taylor-Horner on the vector: t = v + (Ah t)/k, k=K..1.

#define KTERMS 14              // per half-pass; ||A/2|| <= ~2.9 -> trunc ~1e-5
#define MDIM   16
#define DICT   64
#define NROW   8
#define BPAIRS_PER_BLOCK 128   // 128 threads -> 256 b's per block

__constant__ float INVK[KTERMS + 1] = {
    0.f,
    1.f/1,  1.f/2,  1.f/3,  1.f/4,  1.f/5,  1.f/6,  1.f/7,
    1.f/8,  1.f/9,  1.f/10, 1.f/11, 1.f/12, 1.f/13, 1.f/14
};

__device__ __forceinline__ unsigned long long pk2(float lo, float hi) {
    unsigned long long r;
    asm("mov.b64 %0, {%1, %2};" : "=l"(r) : "f"(lo), "f"(hi));
    return r;
}
__device__ __forceinline__ void unpk2(unsigned long long v, float& lo, float& hi) {
    asm("mov.b64 {%0, %1}, %2;" : "=f"(lo), "=f"(hi) : "l"(v));
}
__device__ __forceinline__ unsigned long long fma2(unsigned long long a,
                                                   unsigned long long b,
                                                   unsigned long long c) {
    unsigned long long d;
    asm("fma.rn.f32x2 %0, %1, %2, %3;" : "=l"(d) : "l"(a), "l"(b), "l"(c));
    return d;
}
__device__ __forceinline__ unsigned long long mul2(unsigned long long a,
                                                   unsigned long long b) {
    unsigned long long d;
    asm("mul.rn.f32x2 %0, %1, %2;" : "=l"(d) : "l"(a), "l"(b));
    return d;
}

// One Taylor-Horner half-pass: t = expm(Ah) * v   (Ah packed, row-major 8x8)
__device__ __forceinline__ void horner_pass(const unsigned long long* __restrict__ Ah,
                                            const unsigned long long* __restrict__ v,
                                            unsigned long long* __restrict__ t)
{
#pragma unroll
    for (int n = 0; n < 8; n++) t[n] = v[n];

#pragma unroll 2
    for (int k = KTERMS; k >= 1; --k) {
        unsigned long long w[8];
#pragma unroll
        for (int n = 0; n < 8; n++) w[n] = mul2(Ah[n * 8], t[0]);
#pragma unroll
        for (int j = 1; j < 8; j++) {
#pragma unroll
            for (int n = 0; n < 8; n++)
                w[n] = fma2(Ah[n * 8 + j], t[j], w[n]);
        }
        const float ik = INVK[k];
        const unsigned long long iv = pk2(ik, ik);
#pragma unroll
        for (int n = 0; n < 8; n++) t[n] = fma2(w[n], iv, v[n]);
    }
}

__global__ __launch_bounds__(BPAIRS_PER_BLOCK)
void transop_expm_kernel(const float* __restrict__ x,
                         const float* __restrict__ c,
                         const float* __restrict__ psi,
                         float* __restrict__ out,
                         int Btot)
{
    // psi for this dict, duplicated (v,v) so one f32x2 operand serves a b-pair.
    __shared__ __align__(16) unsigned long long psis[MDIM * 64];
    // half-c pairs: cpk[m*128 + p] = (0.5*c[b0,m], 0.5*c[b1,m])
    __shared__ unsigned long long cpk[MDIM * BPAIRS_PER_BLOCK];

    const int tid = threadIdx.x;
    const int s   = blockIdx.y;                       // dict index 0..63
    const int b0  = blockIdx.x * (2 * BPAIRS_PER_BLOCK) + 2 * tid;
    const int b1  = b0 + 1;

    // ---- stage psi[., s, ., .] : 16 x 64 floats, duplicated into pairs ----
    for (int i = tid; i < MDIM * 64; i += BPAIRS_PER_BLOCK) {
        const int m = i >> 6, e = i & 63;
        const float v = psi[m * (DICT * 64) + s * 64 + e];
        psis[m * 64 + e] = pk2(v, v);
    }
    // ---- stage half-c pairs (builds Ah = A/2 directly) ----
    if (b1 < Btot) {
        const float4* c0 = (const float4*)(c + (size_t)b0 * MDIM);
        const float4* c1 = (const float4*)(c + (size_t)b1 * MDIM);
#pragma unroll
        for (int i = 0; i < 4; i++) {
            const float4 ca = c0[i];
            const float4 cb = c1[i];
            cpk[(4*i + 0) * BPAIRS_PER_BLOCK + tid] = pk2(0.5f*ca.x, 0.5f*cb.x);
            cpk[(4*i + 1) * BPAIRS_PER_BLOCK + tid] = pk2(0.5f*ca.y, 0.5f*cb.y);
            cpk[(4*i + 2) * BPAIRS_PER_BLOCK + tid] = pk2(0.5f*ca.z, 0.5f*cb.z);
            cpk[(4*i + 3) * BPAIRS_PER_BLOCK + tid] = pk2(0.5f*ca.w, 0.5f*cb.w);
        }
    }
    __syncthreads();
    if (b1 >= Btot) return;

    // ---- Ah2[e] = sum_m (c2[m]/2) * psi2[m][e]   (row-major e = n*8 + j) ----
    unsigned long long Ah[64];
#pragma unroll
    for (int e = 0; e < 64; e++) Ah[e] = 0ull;

#pragma unroll 2
    for (int m = 0; m < MDIM; m++) {
        const unsigned long long cm = cpk[m * BPAIRS_PER_BLOCK + tid];
        const ulonglong2* pp = (const ulonglong2*)(psis + m * 64);
#pragma unroll
        for (int e2 = 0; e2 < 32; e2++) {
            const ulonglong2 pv = pp[e2];          // LDS.128, warp-broadcast
            Ah[2*e2 + 0] = fma2(cm, pv.x, Ah[2*e2 + 0]);
            Ah[2*e2 + 1] = fma2(cm, pv.y, Ah[2*e2 + 1]);
        }
    }

    // ---- load x pair: x[b, s*8 .. s*8+7] for b0 and b1 ----
    const float4* xa4 = (const float4*)(x + (size_t)b0 * (DICT * NROW) + s * NROW);
    const float4* xb4 = (const float4*)(x + (size_t)b1 * (DICT * NROW) + s * NROW);
    const float4 a0 = xa4[0], a1 = xa4[1];
    const float4 q0 = xb4[0], q1 = xb4[1];
    unsigned long long xv[8] = {
        pk2(a0.x, q0.x), pk2(a0.y, q0.y), pk2(a0.z, q0.z), pk2(a0.w, q0.w),
        pk2(a1.x, q1.x), pk2(a1.y, q1.y), pk2(a1.z, q1.z), pk2(a1.w, q1.w)
    };

    // ---- two half-passes: u = expm(Ah)x ; t = expm(Ah)u ----
    unsigned long long u[8], t[8];
    horner_pass(Ah, xv, u);
    horner_pass(Ah, u, t);

    // ---- unpack and store both rows ----
    float lo[8], hi[8];
#pragma unroll
    for (int n = 0; n < 8; n++) unpk2(t[n], lo[n], hi[n]);

    float4* o0 = (float4*)(out + (size_t)b0 * (DICT * NROW) + s * NROW);
    float4* o1 = (float4*)(out + (size_t)b1 * (DICT * NROW) + s * NROW);
    o0[0] = make_float4(lo[0], lo[1], lo[2], lo[3]);
    o0[1] = make_float4(lo[4], lo[5], lo[6], lo[7]);
    o1[0] = make_float4(hi[0], hi[1], hi[2], hi[3]);
    o1[1] = make_float4(hi[4], hi[5], hi[6], hi[7]);
}

extern "C" void kernel_launch(void* const* d_in, const int* in_sizes, int n_in,
                              void* d_out, int out_size)
{
    if (n_in < 3) return;
    const float* x   = (const float*)d_in[0];   // (B, 512)
    const float* c   = (const float*)d_in[1];   // (B, 16)
    const float* psi = (const float*)d_in[2];   // (16, 64, 8, 8)
    float* out = (float*)d_out;

    const int Btot = in_sizes[0] / (DICT * NROW);           // 8192
    dim3 grid((Btot + 2 * BPAIRS_PER_BLOCK - 1) / (2 * BPAIRS_PER_BLOCK), DICT);
    transop_expm_kernel<<<grid, BPAIRS_PER_BLOCK>>>(x, c, psi, out, Btot);
}

// round 16
// speedup vs baseline: 1.1744x; 1.1744x over previous
#include <cuda_runtime.h>

// TransOp_expm: out[b,s] = expm(sum_m c[b,m]*psi[m,s]) @ x[b,s]
// B=8192, DICT=64, N=8, M=16. Pure fp32, packed f32x2 (two b's per thread).
// Single Taylor-Horner pass on the vector: t = x + (A t)/k, k = K..1.
// (R7 post-mortem: spills at 218 regs were the limiter; dropped the
//  scaling-and-squaring pass (rel_err was 1.8e-7, 500x margin) to free
//  registers and 19% of instructions.)

#define KTERMS 20              // ||A|| tail ~6 -> trunc ~1e-6 rel
#define MDIM   16
#define DICT   64
#define NROW   8
#define BPAIRS_PER_BLOCK 128   // 128 threads -> 256 b's per block

__constant__ float INVK[KTERMS + 1] = {
    0.f,
    1.f/1,  1.f/2,  1.f/3,  1.f/4,  1.f/5,  1.f/6,  1.f/7,
    1.f/8,  1.f/9,  1.f/10, 1.f/11, 1.f/12, 1.f/13, 1.f/14,
    1.f/15, 1.f/16, 1.f/17, 1.f/18, 1.f/19, 1.f/20
};

__device__ __forceinline__ unsigned long long pk2(float lo, float hi) {
    unsigned long long r;
    asm("mov.b64 %0, {%1, %2};" : "=l"(r) : "f"(lo), "f"(hi));
    return r;
}
__device__ __forceinline__ void unpk2(unsigned long long v, float& lo, float& hi) {
    asm("mov.b64 {%0, %1}, %2;" : "=f"(lo), "=f"(hi) : "l"(v));
}
__device__ __forceinline__ unsigned long long fma2(unsigned long long a,
                                                   unsigned long long b,
                                                   unsigned long long c) {
    unsigned long long d;
    asm("fma.rn.f32x2 %0, %1, %2, %3;" : "=l"(d) : "l"(a), "l"(b), "l"(c));
    return d;
}
__device__ __forceinline__ unsigned long long mul2(unsigned long long a,
                                                   unsigned long long b) {
    unsigned long long d;
    asm("mul.rn.f32x2 %0, %1, %2;" : "=l"(d) : "l"(a), "l"(b));
    return d;
}

__global__ __launch_bounds__(BPAIRS_PER_BLOCK, 2)
void transop_expm_kernel(const float* __restrict__ x,
                         const float* __restrict__ c,
                         const float* __restrict__ psi,
                         float* __restrict__ out,
                         int Btot)
{
    // psi for this dict, duplicated (v,v) so one f32x2 operand serves a b-pair.
    __shared__ __align__(16) unsigned long long psis[MDIM * 64];
    // c pairs: cpk[m*128 + p] = (c[b0,m], c[b1,m])
    __shared__ unsigned long long cpk[MDIM * BPAIRS_PER_BLOCK];

    const int tid = threadIdx.x;
    const int s   = blockIdx.y;                       // dict index 0..63
    const int b0  = blockIdx.x * (2 * BPAIRS_PER_BLOCK) + 2 * tid;
    const int b1  = b0 + 1;

    // ---- stage psi[., s, ., .] : 16 x 64 floats, duplicated into pairs ----
    for (int i = tid; i < MDIM * 64; i += BPAIRS_PER_BLOCK) {
        const int m = i >> 6, e = i & 63;
        const float v = psi[m * (DICT * 64) + s * 64 + e];
        psis[m * 64 + e] = pk2(v, v);
    }
    // ---- stage c pairs ----
    if (b1 < Btot) {
        const float4* c0 = (const float4*)(c + (size_t)b0 * MDIM);
        const float4* c1 = (const float4*)(c + (size_t)b1 * MDIM);
#pragma unroll
        for (int i = 0; i < 4; i++) {
            const float4 ca = c0[i];
            const float4 cb = c1[i];
            cpk[(4*i + 0) * BPAIRS_PER_BLOCK + tid] = pk2(ca.x, cb.x);
            cpk[(4*i + 1) * BPAIRS_PER_BLOCK + tid] = pk2(ca.y, cb.y);
            cpk[(4*i + 2) * BPAIRS_PER_BLOCK + tid] = pk2(ca.z, cb.z);
            cpk[(4*i + 3) * BPAIRS_PER_BLOCK + tid] = pk2(ca.w, cb.w);
        }
    }
    __syncthreads();
    if (b1 >= Btot) return;

    // ---- A2[e] = sum_m c2[m] * psi2[m][e]   (row-major e = n*8 + j) ----
    unsigned long long A[64];
#pragma unroll
    for (int e = 0; e < 64; e++) A[e] = 0ull;

#pragma unroll 2
    for (int m = 0; m < MDIM; m++) {
        const unsigned long long cm = cpk[m * BPAIRS_PER_BLOCK + tid];
        const ulonglong2* pp = (const ulonglong2*)(psis + m * 64);
#pragma unroll
        for (int e2 = 0; e2 < 32; e2++) {
            const ulonglong2 pv = pp[e2];          // LDS.128, warp-broadcast
            A[2*e2 + 0] = fma2(cm, pv.x, A[2*e2 + 0]);
            A[2*e2 + 1] = fma2(cm, pv.y, A[2*e2 + 1]);
        }
    }

    // ---- load x pair: x[b, s*8 .. s*8+7] for b0 and b1 ----
    const float4* xa4 = (const float4*)(x + (size_t)b0 * (DICT * NROW) + s * NROW);
    const float4* xb4 = (const float4*)(x + (size_t)b1 * (DICT * NROW) + s * NROW);
    const float4 a0 = xa4[0], a1 = xa4[1];
    const float4 q0 = xb4[0], q1 = xb4[1];
    unsigned long long xv[8] = {
        pk2(a0.x, q0.x), pk2(a0.y, q0.y), pk2(a0.z, q0.z), pk2(a0.w, q0.w),
        pk2(a1.x, q1.x), pk2(a1.y, q1.y), pk2(a1.z, q1.z), pk2(a1.w, q1.w)
    };

    // ---- vector Taylor-Horner: t = x + (A t) * (1/k), k = K..1 ----
    unsigned long long t[8];
#pragma unroll
    for (int n = 0; n < 8; n++) t[n] = xv[n];

#pragma unroll 2
    for (int k = KTERMS; k >= 1; --k) {
        unsigned long long w[8];
#pragma unroll
        for (int n = 0; n < 8; n++) w[n] = mul2(A[n * 8], t[0]);
#pragma unroll
        for (int j = 1; j < 8; j++) {
#pragma unroll
            for (int n = 0; n < 8; n++)
                w[n] = fma2(A[n * 8 + j], t[j], w[n]);
        }
        const float ik = INVK[k];
        const unsigned long long iv = pk2(ik, ik);
#pragma unroll
        for (int n = 0; n < 8; n++) t[n] = fma2(w[n], iv, xv[n]);
    }

    // ---- unpack and store both rows ----
    float lo[8], hi[8];
#pragma unroll
    for (int n = 0; n < 8; n++) unpk2(t[n], lo[n], hi[n]);

    float4* o0 = (float4*)(out + (size_t)b0 * (DICT * NROW) + s * NROW);
    float4* o1 = (float4*)(out + (size_t)b1 * (DICT * NROW) + s * NROW);
    o0[0] = make_float4(lo[0], lo[1], lo[2], lo[3]);
    o0[1] = make_float4(lo[4], lo[5], lo[6], lo[7]);
    o1[0] = make_float4(hi[0], hi[1], hi[2], hi[3]);
    o1[1] = make_float4(hi[4], hi[5], hi[6], hi[7]);
}

extern "C" void kernel_launch(void* const* d_in, const int* in_sizes, int n_in,
                              void* d_out, int out_size)
{
    if (n_in < 3) return;
    const float* x   = (const float*)d_in[0];   // (B, 512)
    const float* c   = (const float*)d_in[1];   // (B, 16)
    const float* psi = (const float*)d_in[2];   // (16, 64, 8, 8)
    float* out = (float*)d_out;

    const int Btot = in_sizes[0] / (DICT * NROW);           // 8192
    dim3 grid((Btot + 2 * BPAIRS_PER_BLOCK - 1) / (2 * BPAIRS_PER_BLOCK), DICT);
    transop_expm_kernel<<<grid, BPAIRS_PER_BLOCK>>>(x, c, psi, out, Btot);
}